// round 15
// baseline (speedup 1.0000x reference)
#include <cuda_runtime.h>
#include <cstdint>

// ---------------------------------------------------------------------------
// Problem constants
// ---------------------------------------------------------------------------
#define NUM_CLASSES 80
#define B_IMG 8
#define NTOT 20460            // total anchors per image across 5 levels
#define NQUAD 5115            // NTOT/4
#define TOPK 1000
#define MAX_PER_IMG 100
#define K_CAP 16              // phase-A per-class pick cap
#define IMG_H 768.0f
#define IMG_W 1280.0f
#define CLS_OFFSET 4096.0f
#define MAX_RATIO_ANCHOR 13.815510557964274f   // |log(1e-6)|
#define MAX_RATIO_BBOX   4.135166556742356f    // |log(16/1000)|

__device__ __constant__ int   c_HW[5]     = {15360, 3840, 960, 240, 60};
__device__ __constant__ int   c_W[5]      = {160, 80, 40, 20, 10};
__device__ __constant__ int   c_off[5]    = {0, 15360, 19200, 20160, 20400};
__device__ __constant__ int   c_qoff[5]   = {0, 3840, 4800, 5040, 5100};
__device__ __constant__ float c_stride[5] = {8.f, 16.f, 32.f, 64.f, 128.f};

// ---------------------------------------------------------------------------
// Scratch (device globals; no runtime allocation allowed)
// ---------------------------------------------------------------------------
__device__ float4   g_part[B_IMG * 4 * NQUAD];  // per-chunk class maxima
__device__ float4   g_key4[B_IMG * NQUAD];      // per-anchor masked max score
__device__ unsigned g_rowinfo[B_IMG * 1024];    // (mask<<31)|(level<<28)|local_r
__device__ float    g_sc[B_IMG * NUM_CLASSES * 1024]; // persisted suppressed state (open classes)
__device__ float4   g_boxes[B_IMG * 1024];      // decoded proposals

// per-class NMS pick lists
__device__ float          g_pick_s[B_IMG * NUM_CLASSES * MAX_PER_IMG];
__device__ unsigned short g_pick_r[B_IMG * NUM_CLASSES * MAX_PER_IMG];
__device__ int            g_pick_cnt[B_IMG * NUM_CLASSES];
__device__ int            g_pick_stk[B_IMG * NUM_CLASSES];
__device__ int            g_open[B_IMG * NUM_CLASSES];   // capped w/ state written back
__device__ int            g_need[B_IMG * NUM_CLASSES];   // merge-B: must deepen
__device__ unsigned       g_out100[B_IMG];               // bits of 100th output slot
__device__ int            g_redo;

struct Ptrs { const float* p[20]; };

// ---------------------------------------------------------------------------
// Numerics matching jax
// ---------------------------------------------------------------------------
__device__ __forceinline__ float sigf(float x) {
    if (x >= 0.f) return 1.f / (1.f + expf(-x));
    float e = expf(x);
    return e / (1.f + e);
}
__device__ __forceinline__ float dsigf(float x) {
    float s = sigf(x);
    return 1.f / (1.f + expf(-s));
}
__device__ __forceinline__ float clampf(float v, float lo, float hi) {
    return fminf(fmaxf(v, lo), hi);
}
// Exact predicate RN(num/den) > 0.5 without the divide (den > 0, num >= 0).
__device__ __forceinline__ bool iou_gt_half(float num, float den) {
    float h = 0.5f * den;
    if (num <= h) return false;
    if (num > h * 1.0000005f) return true;
    return (num / den > 0.5f);
}

// ---------------------------------------------------------------------------
// Kernel 1: partial max over a 20-class chunk, 4 anchors/thread (LDG.128)
// ---------------------------------------------------------------------------
__global__ __launch_bounds__(256) void k_maxscore_part(Ptrs P) {
    if (blockIdx.x == 0 && blockIdx.y == 0 && blockIdx.z == 0 && threadIdx.x == 0)
        g_redo = 0;
    int b  = blockIdx.y;
    int ch = blockIdx.z;
    int q = blockIdx.x * 256 + threadIdx.x;
    if (q >= NQUAD) return;

    int l;
    if      (q < 3840) l = 0;
    else if (q < 4800) l = 1;
    else if (q < 5040) l = 2;
    else if (q < 5100) l = 3;
    else               l = 4;
    int rq  = q - c_qoff[l];
    int HW4 = c_HW[l] >> 2;

    float4 mx = make_float4(-3.402823466e38f, -3.402823466e38f,
                            -3.402823466e38f, -3.402823466e38f);
    const float4* cp = (const float4*)P.p[4 * l]
                     + ((size_t)b * NUM_CLASSES + ch * 20) * HW4 + rq;
    #pragma unroll 20
    for (int c = 0; c < 20; c++) {
        float4 v = cp[(size_t)c * HW4];
        mx.x = fmaxf(mx.x, v.x);
        mx.y = fmaxf(mx.y, v.y);
        mx.z = fmaxf(mx.z, v.z);
        mx.w = fmaxf(mx.w, v.w);
    }
    g_part[((size_t)b * 4 + ch) * NQUAD + q] = mx;
}

// ---------------------------------------------------------------------------
// Kernel 2: FUSED key computation (combine partial maxima + loc mask +
// double sigmoid) + per-image top-1000 (3-round radix select on the 22-bit
// key delta, count<1000 fallback, stable compaction, bitonic sort) +
// EPILOGUE (per selected row: decode proposal box + rowinfo).
// ---------------------------------------------------------------------------
__global__ __launch_bounds__(1024) void k_select(Ptrs P) {
    int b   = blockIdx.x;
    int tid = threadIdx.x;
    int lane = tid & 31, wid = tid >> 5;

    // ---- prologue: compute keys for this image (was k_mask) ----
    for (int q = tid; q < NQUAD; q += 1024) {
        int l;
        if      (q < 3840) l = 0;
        else if (q < 4800) l = 1;
        else if (q < 5040) l = 2;
        else if (q < 5100) l = 3;
        else               l = 4;
        int rq  = q - c_qoff[l];
        int HW4 = c_HW[l] >> 2;

        float4 m0 = g_part[((size_t)b * 4 + 0) * NQUAD + q];
        float4 m1 = g_part[((size_t)b * 4 + 1) * NQUAD + q];
        float4 m2 = g_part[((size_t)b * 4 + 2) * NQUAD + q];
        float4 m3 = g_part[((size_t)b * 4 + 3) * NQUAD + q];
        float4 mx;
        mx.x = fmaxf(fmaxf(m0.x, m1.x), fmaxf(m2.x, m3.x));
        mx.y = fmaxf(fmaxf(m0.y, m1.y), fmaxf(m2.y, m3.y));
        mx.z = fmaxf(fmaxf(m0.z, m1.z), fmaxf(m2.z, m3.z));
        mx.w = fmaxf(fmaxf(m0.w, m1.w), fmaxf(m2.w, m3.w));

        float4 lv = *((const float4*)P.p[4 * l + 3] + (size_t)b * HW4 + rq);
        float4 key;
        key.x = (sigf(lv.x) >= 0.01f) ? dsigf(mx.x) : 0.f;
        key.y = (sigf(lv.y) >= 0.01f) ? dsigf(mx.y) : 0.f;
        key.z = (sigf(lv.z) >= 0.01f) ? dsigf(mx.z) : 0.f;
        key.w = (sigf(lv.w) >= 0.01f) ? dsigf(mx.w) : 0.f;
        g_key4[(size_t)b * NQUAD + q] = key;
    }
    __syncthreads();

    const unsigned* keys = reinterpret_cast<const unsigned*>(g_key4) + (size_t)b * NTOT;

    __shared__ unsigned hist[256];
    __shared__ unsigned sfx[256];
    __shared__ unsigned s_prefix;
    __shared__ int s_m;
    __shared__ int s_done;
    __shared__ unsigned long long sel[1024];
    __shared__ int warp_tot[32];
    __shared__ int warp_scan[32];
    __shared__ int s_fill;
    __shared__ int s_runeq;

    if (tid == 0) { s_prefix = 0u; s_m = TOPK; s_done = 0; }
    __syncthreads();

    const int SHIFTS[3] = {14, 6, 0};
    const unsigned BMASK[3] = {0xFFu, 0xFFu, 0x3Fu};

    for (int round = 0; round < 3; round++) {
        if (s_done) break;
        int shift = SHIFTS[round];
        if (tid < 256) hist[tid] = 0u;
        __syncthreads();
        unsigned pfx = s_prefix;
        unsigned pmask = (round == 0) ? 0u
                        : (round == 1 ? 0x3FC000u : 0x3FFFC0u);
        int mcur = s_m;
        for (int i = tid; i < 20480; i += 1024) {
            bool v = i < NTOT;
            unsigned k = v ? keys[i] : 0u;
            bool nz = v && (k != 0u);
            unsigned delta = k - 0x3F000000u;
            bool act = nz && ((delta & pmask) == pfx);
            unsigned bin = (delta >> shift) & BMASK[round];
            unsigned am = __ballot_sync(0xFFFFFFFFu, act);
            if (act) {
                unsigned peers = __match_any_sync(am, bin);
                if (lane == __ffs(peers) - 1)
                    atomicAdd(&hist[bin], (unsigned)__popc(peers));
            }
        }
        __syncthreads();
        if (wid == 0) {
            unsigned carry = 0;
            #pragma unroll
            for (int ch = 7; ch >= 0; ch--) {
                unsigned v = hist[ch * 32 + lane];
                #pragma unroll
                for (int d = 1; d < 32; d <<= 1) {
                    unsigned o = __shfl_down_sync(0xFFFFFFFFu, v, d);
                    if (lane + d < 32) v += o;
                }
                sfx[ch * 32 + lane] = v + carry;
                carry += __shfl_sync(0xFFFFFFFFu, v, 0);
            }
        }
        __syncthreads();
        if (round == 0 && tid == 0) {
            if (sfx[0] < (unsigned)TOPK) {
                s_prefix = 0xFFFFFFFFu;         // sentinel: T = 0
                s_m = TOPK - (int)sfx[0];
                s_done = 1;
            }
        }
        __syncthreads();
        if (s_done) break;
        if (tid < 256) {
            unsigned S = sfx[tid];
            unsigned above = S - hist[tid];
            if (S >= (unsigned)mcur && above < (unsigned)mcur) {
                s_prefix = pfx | ((unsigned)tid << shift);
                s_m = mcur - (int)above;
            }
        }
        __syncthreads();
    }

    unsigned T = (s_prefix == 0xFFFFFFFFu) ? 0u : (0x3F000000u + s_prefix);
    int meq = s_m;

    sel[tid] = 0ull;
    if (tid == 0) { s_fill = 0; s_runeq = 0; }
    __syncthreads();

    for (int base = 0; base < NTOT; base += 1024) {
        int i = base + tid;
        bool valid = i < NTOT;
        unsigned k = valid ? keys[i] : 0u;
        bool gt = valid && (k > T);
        bool eq = valid && (k == T);
        unsigned balgt = __ballot_sync(0xFFFFFFFFu, gt);
        if (balgt) {
            int leader = __ffs(balgt) - 1;
            int basep = 0;
            if (lane == leader) basep = atomicAdd(&s_fill, __popc(balgt));
            basep = __shfl_sync(0xFFFFFFFFu, basep, leader);
            if (gt) {
                int p = basep + __popc(balgt & ((1u << lane) - 1u));
                sel[p] = (((unsigned long long)k) << 32) |
                         (unsigned long long)(0xFFFFFFFFu - (unsigned)i);
            }
        }
        unsigned bal = __ballot_sync(0xFFFFFFFFu, eq);
        if (lane == 0) warp_tot[wid] = __popc(bal);
        __syncthreads();
        if (wid == 0) {
            int v = warp_tot[lane];
            #pragma unroll
            for (int d = 1; d < 32; d <<= 1) {
                int n = __shfl_up_sync(0xFFFFFFFFu, v, d);
                if (lane >= d) v += n;
            }
            warp_scan[lane] = v;
        }
        __syncthreads();
        int wbase = (wid == 0) ? 0 : warp_scan[wid - 1];
        int rank = s_runeq + wbase + __popc(bal & ((1u << lane) - 1u));
        if (eq && rank < meq) {
            int p = atomicAdd(&s_fill, 1);
            sel[p] = (((unsigned long long)k) << 32) |
                     (unsigned long long)(0xFFFFFFFFu - (unsigned)i);
        }
        __syncthreads();
        if (tid == 0) s_runeq += warp_scan[31];
        __syncthreads();
    }

    for (int k2 = 2; k2 <= 1024; k2 <<= 1) {
        for (int j = k2 >> 1; j > 0; j >>= 1) {
            __syncthreads();
            int ixj = tid ^ j;
            if (ixj > tid) {
                unsigned long long va = sel[tid], vb = sel[ixj];
                bool up = ((tid & k2) == 0);
                if (up ? (va < vb) : (va > vb)) { sel[tid] = vb; sel[ixj] = va; }
            }
        }
    }
    __syncthreads();
    int a = (int)(0xFFFFFFFFu - (unsigned)(sel[tid] & 0xFFFFFFFFull));

    // ---- epilogue: decode box + rowinfo for selected rows (tid < TOPK) ----
    if (tid < TOPK) {
        int l;
        if      (a < 15360) l = 0;
        else if (a < 19200) l = 1;
        else if (a < 20160) l = 2;
        else if (a < 20400) l = 3;
        else                l = 4;
        int r  = a - c_off[l];
        int HW = c_HW[l];
        int W  = c_W[l];
        int yi = r / W;
        int xi = r - yi * W;

        const float* bb  = P.p[4 * l + 1];
        const float* shp = P.p[4 * l + 2];
        const float* loc = P.p[4 * l + 3];

        unsigned mask = (sigf(loc[(size_t)b * HW + r]) >= 0.01f) ? 1u : 0u;
        g_rowinfo[b * 1024 + tid] = (mask << 31) | ((unsigned)l << 28) | (unsigned)r;

        float st = c_stride[l];
        float xx = (float)xi * st, yy = (float)yi * st;
        float pw = 4.f * st;
        float dw = clampf(shp[((size_t)b * 2 + 0) * HW + r], -MAX_RATIO_ANCHOR, MAX_RATIO_ANCHOR);
        float dh = clampf(shp[((size_t)b * 2 + 1) * HW + r], -MAX_RATIO_ANCHOR, MAX_RATIO_ANCHOR);
        float aw = pw * expf(dw);
        float ah = pw * expf(dh);
        float ax1 = xx - 0.5f * aw, ay1 = yy - 0.5f * ah;
        float ax2 = xx + 0.5f * aw, ay2 = yy + 0.5f * ah;
        float px = (ax1 + ax2) * 0.5f, py = (ay1 + ay2) * 0.5f;
        float w2 = ax2 - ax1,          h2 = ay2 - ay1;
        float dx  = bb[((size_t)b * 4 + 0) * HW + r];
        float dy  = bb[((size_t)b * 4 + 1) * HW + r];
        float dw2 = clampf(bb[((size_t)b * 4 + 2) * HW + r], -MAX_RATIO_BBOX, MAX_RATIO_BBOX);
        float dh2 = clampf(bb[((size_t)b * 4 + 3) * HW + r], -MAX_RATIO_BBOX, MAX_RATIO_BBOX);
        float gx = px + w2 * dx;
        float gy = py + h2 * dy;
        float gw = w2 * expf(dw2);
        float gh = h2 * expf(dh2);
        float x1 = clampf(gx - 0.5f * gw, 0.f, IMG_W);
        float y1 = clampf(gy - 0.5f * gh, 0.f, IMG_H);
        float x2 = clampf(gx + 0.5f * gw, 0.f, IMG_W);
        float y2 = clampf(gy + 0.5f * gh, 0.f, IMG_H);
        g_boxes[b * 1024 + tid] = make_float4(x1, y1, x2, y2);
    }
}

// ---------------------------------------------------------------------------
// Kernel 3: per-class greedy NMS with FUSED score gather. 256 threads per
// (image, class); each thread owns 4 entries (j = tid + 256*k) -- doubled
// warps per block vs R14 cuts registers and feeds the MUFU pipe during the
// fused dsigf init while giving 2x latency hiding in the serial rounds.
// mode 0 (phase A): gather raw cls logits (L2-resident after k_maxscore) and
// compute s = dsigf(v) inline (thresholded, masked). Cap K_CAP; if capped
// ("open"), persist suppressed scores to g_sc so phase C resumes exactly.
// mode 1 (phase C): only needed classes; load persisted state from g_sc;
// EARLY-STOP when the next pick's score bits drop below g_out100[b].
// Argmax: nonzero scores in (0.5, 0.7312) -> (bits-0x3F000000)<<10 | (1023-j)
// gives (score desc, j asc) in ONE __reduce_max_sync. Suppression predicate
// is division-free (iou_gt_half). Sticky degenerate picks (survive own
// suppression; reference re-picks forever) recorded & stopped via sdeg.
// ---------------------------------------------------------------------------
__global__ __launch_bounds__(256) void k_classnms(Ptrs P, int mode) {
    int c = blockIdx.x;
    int b = blockIdx.y;
    int idx = b * NUM_CLASSES + c;
    if (mode == 1 && (g_redo == 0 || g_need[idx] == 0)) return;
    int tid = threadIdx.x;
    int lane = tid & 31, wid = tid >> 5;

    __shared__ float4 sbox[TOPK];
    __shared__ float  sarea[TOPK];
    __shared__ unsigned char sdeg[TOPK];   // 1 = degenerate (survives self)
    __shared__ unsigned wtop[2][8];

    float offc = CLS_OFFSET * (float)c;
    unsigned stop_delta = 0u;
    if (mode == 1) {
        unsigned ob = g_out100[b];
        stop_delta = (ob > 0x3F000000u) ? (ob - 0x3F000000u) : 0u;
    }

    float4  rb[4];
    float   ra[4];
    unsigned comp[4];                  // (bits-0x3F000000)<<10 | (1023-j); 0 = dead
    float* sp = g_sc + ((size_t)idx) * 1024;
    #pragma unroll
    for (int k = 0; k < 4; k++) {
        int j = tid + 256 * k;
        float4 q = (j < TOPK) ? g_boxes[b * 1024 + j] : make_float4(0.f, 0.f, 0.f, 0.f);
        q.x += offc; q.y += offc; q.z += offc; q.w += offc;
        float ar = (q.z - q.x) * (q.w - q.y);
        rb[k] = q; ra[k] = ar;
        if (j < TOPK) {
            sbox[j] = q; sarea[j] = ar;
            sdeg[j] = iou_gt_half(ar, ar + 1e-6f) ? 0 : 1;
        }
        float s = 0.f;
        if (j < TOPK) {
            if (mode == 0) {
                unsigned info = g_rowinfo[b * 1024 + j];
                if (info >> 31) {
                    int l = (info >> 28) & 7;
                    int r = (int)(info & 0x0FFFFFFFu);
                    float v = P.p[4 * l][((size_t)b * NUM_CLASSES + c) * c_HW[l] + r];
                    s = dsigf(v);
                    if (!(s > 0.05f)) s = 0.f;
                }
            } else {
                s = sp[j];
            }
        }
        unsigned bits = __float_as_uint(s);
        comp[k] = (bits > 0x3F000000u)
                ? (((bits - 0x3F000000u) << 10) | (unsigned)(1023 - j)) : 0u;
    }
    __syncthreads();

    int cap = (mode == 1) ? MAX_PER_IMG : K_CAP;
    int cnt = (mode == 1) ? g_pick_cnt[idx] : 0;
    float*          ps = g_pick_s + (size_t)idx * MAX_PER_IMG;
    unsigned short* pr = g_pick_r + (size_t)idx * MAX_PER_IMG;

    int sticky = 0, open = 0, rnd = 0;

    for (;;) {
        unsigned c1 = 0u;
        #pragma unroll
        for (int k = 0; k < 4; k++) c1 = max(c1, comp[k]);
        unsigned M = __reduce_max_sync(0xFFFFFFFFu, c1);
        if (lane == 0) wtop[rnd & 1][wid] = M;
        __syncthreads();
        unsigned M1 = max(max(max(wtop[rnd & 1][0], wtop[rnd & 1][1]),
                              max(wtop[rnd & 1][2], wtop[rnd & 1][3])),
                          max(max(wtop[rnd & 1][4], wtop[rnd & 1][5]),
                              max(wtop[rnd & 1][6], wtop[rnd & 1][7])));
        rnd++;
        if (M1 == 0u) break;                                // class exhausted
        if (mode == 1 && (M1 >> 10) < stop_delta) break;    // provably irrelevant
        if (cnt == cap) { open = 1; break; }                // capped (pending)

        int j1 = 1023 - (int)(M1 & 1023u);
        if (tid == 0) {
            ps[cnt] = __uint_as_float((M1 >> 10) + 0x3F000000u);
            pr[cnt] = (unsigned short)j1;
        }
        cnt++;
        if (sdeg[j1]) { sticky = 1; break; }                // survives itself

        float4 p1 = sbox[j1];
        float ar1 = sarea[j1];
        #pragma unroll
        for (int k = 0; k < 4; k++) {
            if (comp[k] != 0u) {
                float4 q = rb[k];
                float ltx = fmaxf(p1.x, q.x), lty = fmaxf(p1.y, q.y);
                float rbx = fminf(p1.z, q.z), rby = fminf(p1.w, q.w);
                float ww = fmaxf(rbx - ltx, 0.f), hh = fmaxf(rby - lty, 0.f);
                float inter = ww * hh;
                float den = ar1 + ra[k] - inter + 1e-6f;
                if (iou_gt_half(inter, den)) comp[k] = 0u;
            }
        }
    }

    // open classes persist suppressed state so phase C can resume exactly
    if (mode == 0 && open) {
        #pragma unroll
        for (int k = 0; k < 4; k++) {
            int j = tid + 256 * k;
            if (j < TOPK)
                sp[j] = comp[k] ? __uint_as_float((comp[k] >> 10) + 0x3F000000u) : 0.f;
        }
    }

    if (tid == 0) {
        g_pick_cnt[idx] = cnt;
        g_pick_stk[idx] = sticky;
        g_open[idx] = (mode == 0) ? open : 0;
    }
}

// ---------------------------------------------------------------------------
// Kernel 4: per-image merge as a SORT (greedy merge of sorted lists == sorted
// prefix; first sticky in sorted order repeats forever). Sticky bit embedded
// in low word (keys unique -> never affects ordering).
// Phase B (final=0): need[c] = open[c] && last_bits >= bits(100th output);
// also stores bits(100th output) in g_out100[b] for phase-C early stop.
// Phase D (final=1): only if g_redo.
// ---------------------------------------------------------------------------
__global__ __launch_bounds__(1024) void k_merge(float* __restrict__ out, int final_pass) {
    if (final_pass && g_redo == 0) return;
    int b = blockIdx.x;
    int tid = threadIdx.x;
    int lane = tid & 31, wid = tid >> 5;

    __shared__ unsigned long long arr[2048];
    __shared__ int s_n;
    __shared__ int s_fs;
    __shared__ unsigned      s_last[NUM_CLASSES];
    __shared__ unsigned char s_opn[NUM_CLASSES];

    arr[tid] = 0ull;
    arr[tid + 1024] = 0ull;
    if (tid == 0) { s_n = 0; s_fs = 1 << 30; }
    __syncthreads();

    for (int c = wid; c < NUM_CLASSES; c += 32) {
        int idx = b * NUM_CLASSES + c;
        int cnt = g_pick_cnt[idx];
        int stk = g_pick_stk[idx];
        int base = 0;
        if (lane == 0) {
            base = atomicAdd(&s_n, cnt);
            s_last[c] = cnt ? __float_as_uint(g_pick_s[(size_t)idx * MAX_PER_IMG + cnt - 1]) : 0u;
            s_opn[c] = (unsigned char)g_open[idx];
        }
        base = __shfl_sync(0xFFFFFFFFu, base, 0);
        for (int p = lane; p < cnt; p += 32) {
            unsigned bits = __float_as_uint(g_pick_s[(size_t)idx * MAX_PER_IMG + p]);
            unsigned key  = (unsigned)g_pick_r[(size_t)idx * MAX_PER_IMG + p] * 80u + (unsigned)c;
            unsigned st   = (stk && p == cnt - 1) ? 1u : 0u;
            int pos = base + p;
            if (pos < 2048)
                arr[pos] = ((unsigned long long)bits << 32)
                         | (unsigned long long)(0xFFFFFFFFu - ((key << 1) | st));
        }
    }
    __syncthreads();

    for (int k2 = 2; k2 <= 2048; k2 <<= 1) {
        for (int j = k2 >> 1; j > 0; j >>= 1) {
            int a = ((tid & ~(j - 1)) << 1) | (tid & (j - 1));
            int bx = a + j;
            unsigned long long va = arr[a], vb = arr[bx];
            bool desc = ((a & k2) == 0);
            if (desc ? (va < vb) : (va > vb)) { arr[a] = vb; arr[bx] = va; }
            __syncthreads();
        }
    }

    #pragma unroll
    for (int q = 0; q < 2; q++) {
        int i2 = tid + q * 1024;
        unsigned long long e = arr[i2];
        if (e != 0ull) {
            unsigned v = 0xFFFFFFFFu - (unsigned)(e & 0xFFFFFFFFull);
            if (v & 1u) atomicMin(&s_fs, i2);
        }
    }
    __syncthreads();

    int fs = s_fs;
    int ncand = s_n; if (ncand > 2048) ncand = 2048;

    float* outB = out + 8;
    float* outS = outB + B_IMG * MAX_PER_IMG * 4;
    float* outC = outS + B_IMG * MAX_PER_IMG;

    unsigned out100 = 0u;
    {
        int src99 = (99 <= fs) ? 99 : fs;
        bool has99 = (fs < 2048) ? true : (99 < ncand);
        if (has99) out100 = (unsigned)(arr[src99] >> 32);
    }

    if (tid < MAX_PER_IMG) {
        int t = tid;
        int src = (t <= fs) ? t : fs;
        bool has = (fs < 2048) ? true : (t < ncand);
        int o = b * MAX_PER_IMG + t;
        if (has) {
            unsigned long long e = arr[src];
            unsigned v = 0xFFFFFFFFu - (unsigned)(e & 0xFFFFFFFFull);
            unsigned key = v >> 1;
            int c = (int)(key % 80u);
            int r = (int)(key / 80u);
            float4 bx = g_boxes[b * 1024 + r];
            outB[o * 4 + 0] = bx.x;
            outB[o * 4 + 1] = bx.y;
            outB[o * 4 + 2] = bx.z;
            outB[o * 4 + 3] = bx.w;
            outS[o] = __uint_as_float((unsigned)(e >> 32));
            outC[o] = (float)c;
        } else {
            outB[o * 4 + 0] = 0.f; outB[o * 4 + 1] = 0.f;
            outB[o * 4 + 2] = 0.f; outB[o * 4 + 3] = 0.f;
            outS[o] = 0.f;
            outC[o] = -1.f;
        }
    }
    if (tid == 0) {
        int ndet = (fs < 2048) ? MAX_PER_IMG : (ncand < MAX_PER_IMG ? ncand : MAX_PER_IMG);
        out[b] = (float)ndet;
        if (!final_pass) g_out100[b] = out100;
    }

    if (!final_pass && tid < NUM_CLASSES) {
        int need = (s_opn[tid] && s_last[tid] >= out100) ? 1 : 0;
        g_need[b * NUM_CLASSES + tid] = need;
        if (need) g_redo = 1;
    }
}

// ---------------------------------------------------------------------------
// Launch
// ---------------------------------------------------------------------------
extern "C" void kernel_launch(void* const* d_in, const int* in_sizes, int n_in,
                              void* d_out, int out_size) {
    (void)in_sizes; (void)n_in; (void)out_size;
    Ptrs P;
    for (int i = 0; i < 20; i++) P.p[i] = (const float*)d_in[i];
    float* out = (float*)d_out;

    dim3 gp((NQUAD + 255) / 256, B_IMG, 4);
    k_maxscore_part<<<gp, 256>>>(P);
    k_select<<<B_IMG, 1024>>>(P);                          // keys + top1000 + box/rowinfo
    k_classnms<<<dim3(NUM_CLASSES, B_IMG), 256>>>(P, 0);   // phase A (fused gather+dsigf)
    k_merge<<<B_IMG, 1024>>>(out, 0);                      // phase B (+ need/out100)
    k_classnms<<<dim3(NUM_CLASSES, B_IMG), 256>>>(P, 1);   // phase C (resume, early-stop)
    k_merge<<<B_IMG, 1024>>>(out, 1);                      // phase D (only if redo)
}

// round 16
// speedup vs baseline: 1.0620x; 1.0620x over previous
#include <cuda_runtime.h>
#include <cstdint>

// ---------------------------------------------------------------------------
// Problem constants
// ---------------------------------------------------------------------------
#define NUM_CLASSES 80
#define B_IMG 8
#define NTOT 20460            // total anchors per image across 5 levels
#define NQUAD 5115            // NTOT/4
#define TOPK 1000
#define MAX_PER_IMG 100
#define K_CAP 16              // phase-A per-class pick cap
#define IMG_H 768.0f
#define IMG_W 1280.0f
#define CLS_OFFSET 4096.0f
#define MAX_RATIO_ANCHOR 13.815510557964274f   // |log(1e-6)|
#define MAX_RATIO_BBOX   4.135166556742356f    // |log(16/1000)|

__device__ __constant__ int   c_HW[5]     = {15360, 3840, 960, 240, 60};
__device__ __constant__ int   c_W[5]      = {160, 80, 40, 20, 10};
__device__ __constant__ int   c_off[5]    = {0, 15360, 19200, 20160, 20400};
__device__ __constant__ int   c_qoff[5]   = {0, 3840, 4800, 5040, 5100};
__device__ __constant__ float c_stride[5] = {8.f, 16.f, 32.f, 64.f, 128.f};

// ---------------------------------------------------------------------------
// Scratch (device globals; no runtime allocation allowed)
// ---------------------------------------------------------------------------
__device__ float4   g_part[B_IMG * 4 * NQUAD];  // per-chunk class maxima
__device__ float4   g_key4[B_IMG * NQUAD];      // per-anchor masked max score
__device__ unsigned g_rowinfo[B_IMG * 1024];    // (mask<<31)|(level<<28)|local_r
__device__ float    g_sc[B_IMG * NUM_CLASSES * 1024]; // persisted suppressed state (open classes)
__device__ float4   g_boxes[B_IMG * 1024];      // decoded proposals

// per-class NMS pick lists
__device__ float          g_pick_s[B_IMG * NUM_CLASSES * MAX_PER_IMG];
__device__ unsigned short g_pick_r[B_IMG * NUM_CLASSES * MAX_PER_IMG];
__device__ int            g_pick_cnt[B_IMG * NUM_CLASSES];
__device__ int            g_pick_stk[B_IMG * NUM_CLASSES];
__device__ int            g_open[B_IMG * NUM_CLASSES];   // capped w/ state written back
__device__ int            g_need[B_IMG * NUM_CLASSES];   // merge-B: must deepen
__device__ unsigned       g_out100[B_IMG];               // bits of 100th output slot
__device__ int            g_redo;

struct Ptrs { const float* p[20]; };

// ---------------------------------------------------------------------------
// Numerics matching jax
// ---------------------------------------------------------------------------
__device__ __forceinline__ float sigf(float x) {
    if (x >= 0.f) return 1.f / (1.f + expf(-x));
    float e = expf(x);
    return e / (1.f + e);
}
__device__ __forceinline__ float dsigf(float x) {
    float s = sigf(x);
    return 1.f / (1.f + expf(-s));
}
__device__ __forceinline__ float clampf(float v, float lo, float hi) {
    return fminf(fmaxf(v, lo), hi);
}
// Exact predicate RN(num/den) > 0.5 without the divide (den > 0, num >= 0).
__device__ __forceinline__ bool iou_gt_half(float num, float den) {
    float h = 0.5f * den;
    if (num <= h) return false;
    if (num > h * 1.0000005f) return true;
    return (num / den > 0.5f);
}

// ---------------------------------------------------------------------------
// Kernel 1a: partial max over a 20-class chunk, 4 anchors/thread (LDG.128)
// ---------------------------------------------------------------------------
__global__ __launch_bounds__(256) void k_maxscore_part(Ptrs P) {
    if (blockIdx.x == 0 && blockIdx.y == 0 && blockIdx.z == 0 && threadIdx.x == 0)
        g_redo = 0;
    int b  = blockIdx.y;
    int ch = blockIdx.z;
    int q = blockIdx.x * 256 + threadIdx.x;
    if (q >= NQUAD) return;

    int l;
    if      (q < 3840) l = 0;
    else if (q < 4800) l = 1;
    else if (q < 5040) l = 2;
    else if (q < 5100) l = 3;
    else               l = 4;
    int rq  = q - c_qoff[l];
    int HW4 = c_HW[l] >> 2;

    float4 mx = make_float4(-3.402823466e38f, -3.402823466e38f,
                            -3.402823466e38f, -3.402823466e38f);
    const float4* cp = (const float4*)P.p[4 * l]
                     + ((size_t)b * NUM_CLASSES + ch * 20) * HW4 + rq;
    #pragma unroll 20
    for (int c = 0; c < 20; c++) {
        float4 v = cp[(size_t)c * HW4];
        mx.x = fmaxf(mx.x, v.x);
        mx.y = fmaxf(mx.y, v.y);
        mx.z = fmaxf(mx.z, v.z);
        mx.w = fmaxf(mx.w, v.w);
    }
    g_part[((size_t)b * 4 + ch) * NQUAD + q] = mx;
}

// ---------------------------------------------------------------------------
// Kernel 1b: combine 4 partial maxima + loc mask + double sigmoid -> key
// ---------------------------------------------------------------------------
__global__ __launch_bounds__(256) void k_mask(Ptrs P) {
    int b = blockIdx.y;
    int q = blockIdx.x * 256 + threadIdx.x;
    if (q >= NQUAD) return;

    int l;
    if      (q < 3840) l = 0;
    else if (q < 4800) l = 1;
    else if (q < 5040) l = 2;
    else if (q < 5100) l = 3;
    else               l = 4;
    int rq  = q - c_qoff[l];
    int HW4 = c_HW[l] >> 2;

    float4 m0 = g_part[((size_t)b * 4 + 0) * NQUAD + q];
    float4 m1 = g_part[((size_t)b * 4 + 1) * NQUAD + q];
    float4 m2 = g_part[((size_t)b * 4 + 2) * NQUAD + q];
    float4 m3 = g_part[((size_t)b * 4 + 3) * NQUAD + q];
    float4 mx;
    mx.x = fmaxf(fmaxf(m0.x, m1.x), fmaxf(m2.x, m3.x));
    mx.y = fmaxf(fmaxf(m0.y, m1.y), fmaxf(m2.y, m3.y));
    mx.z = fmaxf(fmaxf(m0.z, m1.z), fmaxf(m2.z, m3.z));
    mx.w = fmaxf(fmaxf(m0.w, m1.w), fmaxf(m2.w, m3.w));

    float4 lv = *((const float4*)P.p[4 * l + 3] + (size_t)b * HW4 + rq);
    float4 key;
    key.x = (sigf(lv.x) >= 0.01f) ? dsigf(mx.x) : 0.f;
    key.y = (sigf(lv.y) >= 0.01f) ? dsigf(mx.y) : 0.f;
    key.z = (sigf(lv.z) >= 0.01f) ? dsigf(mx.z) : 0.f;
    key.w = (sigf(lv.w) >= 0.01f) ? dsigf(mx.w) : 0.f;
    g_key4[(size_t)b * NQUAD + q] = key;
}

// ---------------------------------------------------------------------------
// Kernel 2: per-image top-1000 by (key desc, idx asc). 3-round radix select
// on the 22-bit key delta + count<1000 fallback, stable compaction, bitonic.
// EPILOGUE (fused): per selected row, decode proposal box + rowinfo.
// ---------------------------------------------------------------------------
__global__ __launch_bounds__(1024) void k_select(Ptrs P) {
    int b   = blockIdx.x;
    int tid = threadIdx.x;
    int lane = tid & 31, wid = tid >> 5;
    const unsigned* keys = reinterpret_cast<const unsigned*>(g_key4) + (size_t)b * NTOT;

    __shared__ unsigned hist[256];
    __shared__ unsigned sfx[256];
    __shared__ unsigned s_prefix;
    __shared__ int s_m;
    __shared__ int s_done;
    __shared__ unsigned long long sel[1024];
    __shared__ int warp_tot[32];
    __shared__ int warp_scan[32];
    __shared__ int s_fill;
    __shared__ int s_runeq;

    if (tid == 0) { s_prefix = 0u; s_m = TOPK; s_done = 0; }
    __syncthreads();

    const int SHIFTS[3] = {14, 6, 0};
    const unsigned BMASK[3] = {0xFFu, 0xFFu, 0x3Fu};

    for (int round = 0; round < 3; round++) {
        if (s_done) break;
        int shift = SHIFTS[round];
        if (tid < 256) hist[tid] = 0u;
        __syncthreads();
        unsigned pfx = s_prefix;
        unsigned pmask = (round == 0) ? 0u
                        : (round == 1 ? 0x3FC000u : 0x3FFFC0u);
        int mcur = s_m;
        for (int i = tid; i < 20480; i += 1024) {
            bool v = i < NTOT;
            unsigned k = v ? keys[i] : 0u;
            bool nz = v && (k != 0u);
            unsigned delta = k - 0x3F000000u;
            bool act = nz && ((delta & pmask) == pfx);
            unsigned bin = (delta >> shift) & BMASK[round];
            unsigned am = __ballot_sync(0xFFFFFFFFu, act);
            if (act) {
                unsigned peers = __match_any_sync(am, bin);
                if (lane == __ffs(peers) - 1)
                    atomicAdd(&hist[bin], (unsigned)__popc(peers));
            }
        }
        __syncthreads();
        if (wid == 0) {
            unsigned carry = 0;
            #pragma unroll
            for (int ch = 7; ch >= 0; ch--) {
                unsigned v = hist[ch * 32 + lane];
                #pragma unroll
                for (int d = 1; d < 32; d <<= 1) {
                    unsigned o = __shfl_down_sync(0xFFFFFFFFu, v, d);
                    if (lane + d < 32) v += o;
                }
                sfx[ch * 32 + lane] = v + carry;
                carry += __shfl_sync(0xFFFFFFFFu, v, 0);
            }
        }
        __syncthreads();
        if (round == 0 && tid == 0) {
            if (sfx[0] < (unsigned)TOPK) {
                s_prefix = 0xFFFFFFFFu;         // sentinel: T = 0
                s_m = TOPK - (int)sfx[0];
                s_done = 1;
            }
        }
        __syncthreads();
        if (s_done) break;
        if (tid < 256) {
            unsigned S = sfx[tid];
            unsigned above = S - hist[tid];
            if (S >= (unsigned)mcur && above < (unsigned)mcur) {
                s_prefix = pfx | ((unsigned)tid << shift);
                s_m = mcur - (int)above;
            }
        }
        __syncthreads();
    }

    unsigned T = (s_prefix == 0xFFFFFFFFu) ? 0u : (0x3F000000u + s_prefix);
    int meq = s_m;

    sel[tid] = 0ull;
    if (tid == 0) { s_fill = 0; s_runeq = 0; }
    __syncthreads();

    for (int base = 0; base < NTOT; base += 1024) {
        int i = base + tid;
        bool valid = i < NTOT;
        unsigned k = valid ? keys[i] : 0u;
        bool gt = valid && (k > T);
        bool eq = valid && (k == T);
        unsigned balgt = __ballot_sync(0xFFFFFFFFu, gt);
        if (balgt) {
            int leader = __ffs(balgt) - 1;
            int basep = 0;
            if (lane == leader) basep = atomicAdd(&s_fill, __popc(balgt));
            basep = __shfl_sync(0xFFFFFFFFu, basep, leader);
            if (gt) {
                int p = basep + __popc(balgt & ((1u << lane) - 1u));
                sel[p] = (((unsigned long long)k) << 32) |
                         (unsigned long long)(0xFFFFFFFFu - (unsigned)i);
            }
        }
        unsigned bal = __ballot_sync(0xFFFFFFFFu, eq);
        if (lane == 0) warp_tot[wid] = __popc(bal);
        __syncthreads();
        if (wid == 0) {
            int v = warp_tot[lane];
            #pragma unroll
            for (int d = 1; d < 32; d <<= 1) {
                int n = __shfl_up_sync(0xFFFFFFFFu, v, d);
                if (lane >= d) v += n;
            }
            warp_scan[lane] = v;
        }
        __syncthreads();
        int wbase = (wid == 0) ? 0 : warp_scan[wid - 1];
        int rank = s_runeq + wbase + __popc(bal & ((1u << lane) - 1u));
        if (eq && rank < meq) {
            int p = atomicAdd(&s_fill, 1);
            sel[p] = (((unsigned long long)k) << 32) |
                     (unsigned long long)(0xFFFFFFFFu - (unsigned)i);
        }
        __syncthreads();
        if (tid == 0) s_runeq += warp_scan[31];
        __syncthreads();
    }

    for (int k2 = 2; k2 <= 1024; k2 <<= 1) {
        for (int j = k2 >> 1; j > 0; j >>= 1) {
            __syncthreads();
            int ixj = tid ^ j;
            if (ixj > tid) {
                unsigned long long va = sel[tid], vb = sel[ixj];
                bool up = ((tid & k2) == 0);
                if (up ? (va < vb) : (va > vb)) { sel[tid] = vb; sel[ixj] = va; }
            }
        }
    }
    __syncthreads();
    int a = (int)(0xFFFFFFFFu - (unsigned)(sel[tid] & 0xFFFFFFFFull));

    // ---- epilogue: decode box + rowinfo for selected rows (tid < TOPK) ----
    if (tid < TOPK) {
        int l;
        if      (a < 15360) l = 0;
        else if (a < 19200) l = 1;
        else if (a < 20160) l = 2;
        else if (a < 20400) l = 3;
        else                l = 4;
        int r  = a - c_off[l];
        int HW = c_HW[l];
        int W  = c_W[l];
        int yi = r / W;
        int xi = r - yi * W;

        const float* bb  = P.p[4 * l + 1];
        const float* shp = P.p[4 * l + 2];
        const float* loc = P.p[4 * l + 3];

        unsigned mask = (sigf(loc[(size_t)b * HW + r]) >= 0.01f) ? 1u : 0u;
        g_rowinfo[b * 1024 + tid] = (mask << 31) | ((unsigned)l << 28) | (unsigned)r;

        float st = c_stride[l];
        float xx = (float)xi * st, yy = (float)yi * st;
        float pw = 4.f * st;
        float dw = clampf(shp[((size_t)b * 2 + 0) * HW + r], -MAX_RATIO_ANCHOR, MAX_RATIO_ANCHOR);
        float dh = clampf(shp[((size_t)b * 2 + 1) * HW + r], -MAX_RATIO_ANCHOR, MAX_RATIO_ANCHOR);
        float aw = pw * expf(dw);
        float ah = pw * expf(dh);
        float ax1 = xx - 0.5f * aw, ay1 = yy - 0.5f * ah;
        float ax2 = xx + 0.5f * aw, ay2 = yy + 0.5f * ah;
        float px = (ax1 + ax2) * 0.5f, py = (ay1 + ay2) * 0.5f;
        float w2 = ax2 - ax1,          h2 = ay2 - ay1;
        float dx  = bb[((size_t)b * 4 + 0) * HW + r];
        float dy  = bb[((size_t)b * 4 + 1) * HW + r];
        float dw2 = clampf(bb[((size_t)b * 4 + 2) * HW + r], -MAX_RATIO_BBOX, MAX_RATIO_BBOX);
        float dh2 = clampf(bb[((size_t)b * 4 + 3) * HW + r], -MAX_RATIO_BBOX, MAX_RATIO_BBOX);
        float gx = px + w2 * dx;
        float gy = py + h2 * dy;
        float gw = w2 * expf(dw2);
        float gh = h2 * expf(dh2);
        float x1 = clampf(gx - 0.5f * gw, 0.f, IMG_W);
        float y1 = clampf(gy - 0.5f * gh, 0.f, IMG_H);
        float x2 = clampf(gx + 0.5f * gw, 0.f, IMG_W);
        float y2 = clampf(gy + 0.5f * gh, 0.f, IMG_H);
        g_boxes[b * 1024 + tid] = make_float4(x1, y1, x2, y2);
    }
}

// ---------------------------------------------------------------------------
// Kernel 3: per-class greedy NMS (R14 config: 128 threads, 8 entries/thread)
// with FUSED score gather. mode 0 (phase A): gather raw cls logits (L2-
// resident after k_maxscore) and compute s = dsigf(v) inline (thresholded,
// masked). Cap K_CAP; if capped ("open"), persist suppressed scores to g_sc.
// mode 1 (phase C): only needed classes; load persisted state from g_sc;
// EARLY-STOP when the next pick's score bits drop below g_out100[b].
// Argmax: nonzero scores in (0.5, 0.7312) -> (bits-0x3F000000)<<10 | (1023-j)
// gives (score desc, j asc) in ONE __reduce_max_sync. Suppression predicate
// division-free (iou_gt_half). Sticky degenerate picks recorded & stopped.
// ---------------------------------------------------------------------------
__global__ __launch_bounds__(128) void k_classnms(Ptrs P, int mode) {
    int c = blockIdx.x;
    int b = blockIdx.y;
    int idx = b * NUM_CLASSES + c;
    if (mode == 1 && (g_redo == 0 || g_need[idx] == 0)) return;
    int tid = threadIdx.x;
    int lane = tid & 31, wid = tid >> 5;

    __shared__ float4 sbox[TOPK];
    __shared__ float  sarea[TOPK];
    __shared__ unsigned char sdeg[TOPK];   // 1 = degenerate (survives self)
    __shared__ unsigned wtop[2][4];

    float offc = CLS_OFFSET * (float)c;
    unsigned stop_delta = 0u;
    if (mode == 1) {
        unsigned ob = g_out100[b];
        stop_delta = (ob > 0x3F000000u) ? (ob - 0x3F000000u) : 0u;
    }

    float4  rb[8];
    float   ra[8];
    unsigned comp[8];                  // (bits-0x3F000000)<<10 | (1023-j); 0 = dead
    float* sp = g_sc + ((size_t)idx) * 1024;
    #pragma unroll
    for (int k = 0; k < 8; k++) {
        int j = tid + 128 * k;
        float4 q = (j < TOPK) ? g_boxes[b * 1024 + j] : make_float4(0.f, 0.f, 0.f, 0.f);
        q.x += offc; q.y += offc; q.z += offc; q.w += offc;
        float ar = (q.z - q.x) * (q.w - q.y);
        rb[k] = q; ra[k] = ar;
        if (j < TOPK) {
            sbox[j] = q; sarea[j] = ar;
            sdeg[j] = iou_gt_half(ar, ar + 1e-6f) ? 0 : 1;
        }
        float s = 0.f;
        if (j < TOPK) {
            if (mode == 0) {
                unsigned info = g_rowinfo[b * 1024 + j];
                if (info >> 31) {
                    int l = (info >> 28) & 7;
                    int r = (int)(info & 0x0FFFFFFFu);
                    float v = P.p[4 * l][((size_t)b * NUM_CLASSES + c) * c_HW[l] + r];
                    s = dsigf(v);
                    if (!(s > 0.05f)) s = 0.f;
                }
            } else {
                s = sp[j];
            }
        }
        unsigned bits = __float_as_uint(s);
        comp[k] = (bits > 0x3F000000u)
                ? (((bits - 0x3F000000u) << 10) | (unsigned)(1023 - j)) : 0u;
    }
    __syncthreads();

    int cap = (mode == 1) ? MAX_PER_IMG : K_CAP;
    int cnt = (mode == 1) ? g_pick_cnt[idx] : 0;
    float*          ps = g_pick_s + (size_t)idx * MAX_PER_IMG;
    unsigned short* pr = g_pick_r + (size_t)idx * MAX_PER_IMG;

    int sticky = 0, open = 0, rnd = 0;

    for (;;) {
        unsigned c1 = 0u;
        #pragma unroll
        for (int k = 0; k < 8; k++) c1 = max(c1, comp[k]);
        unsigned M = __reduce_max_sync(0xFFFFFFFFu, c1);
        if (lane == 0) wtop[rnd & 1][wid] = M;
        __syncthreads();
        unsigned M1 = max(max(wtop[rnd & 1][0], wtop[rnd & 1][1]),
                          max(wtop[rnd & 1][2], wtop[rnd & 1][3]));
        rnd++;
        if (M1 == 0u) break;                                // class exhausted
        if (mode == 1 && (M1 >> 10) < stop_delta) break;    // provably irrelevant
        if (cnt == cap) { open = 1; break; }                // capped (pending)

        int j1 = 1023 - (int)(M1 & 1023u);
        if (tid == 0) {
            ps[cnt] = __uint_as_float((M1 >> 10) + 0x3F000000u);
            pr[cnt] = (unsigned short)j1;
        }
        cnt++;
        if (sdeg[j1]) { sticky = 1; break; }                // survives itself

        float4 p1 = sbox[j1];
        float ar1 = sarea[j1];
        #pragma unroll
        for (int k = 0; k < 8; k++) {
            if (comp[k] != 0u) {
                float4 q = rb[k];
                float ltx = fmaxf(p1.x, q.x), lty = fmaxf(p1.y, q.y);
                float rbx = fminf(p1.z, q.z), rby = fminf(p1.w, q.w);
                float ww = fmaxf(rbx - ltx, 0.f), hh = fmaxf(rby - lty, 0.f);
                float inter = ww * hh;
                float den = ar1 + ra[k] - inter + 1e-6f;
                if (iou_gt_half(inter, den)) comp[k] = 0u;
            }
        }
    }

    // open classes persist suppressed state so phase C can resume exactly
    if (mode == 0 && open) {
        #pragma unroll
        for (int k = 0; k < 8; k++) {
            int j = tid + 128 * k;
            if (j < TOPK)
                sp[j] = comp[k] ? __uint_as_float((comp[k] >> 10) + 0x3F000000u) : 0.f;
        }
    }

    if (tid == 0) {
        g_pick_cnt[idx] = cnt;
        g_pick_stk[idx] = sticky;
        g_open[idx] = (mode == 0) ? open : 0;
    }
}

// ---------------------------------------------------------------------------
// Kernel 4: per-image merge as a SORT. Bitonic over 2048 with elements
// REGISTER-RESIDENT (thread t owns indices 2t, 2t+1): j==1 is thread-
// internal, j in {2..32} uses warp shuffles (partner thread t^(j/2)), only
// j>=64 touches smem -> 15 smem stages (30 barriers) instead of 66.
// Identical sorted result. First sticky in sorted order repeats forever
// (sticky bit in low word; keys unique so ordering unaffected).
// Phase B (final=0): need[c] = open[c] && last_bits >= bits(100th output);
// stores bits(100th output) in g_out100[b]. Phase D (final=1): only if redo.
// ---------------------------------------------------------------------------
__global__ __launch_bounds__(1024) void k_merge(float* __restrict__ out, int final_pass) {
    if (final_pass && g_redo == 0) return;
    int b = blockIdx.x;
    int tid = threadIdx.x;
    int lane = tid & 31, wid = tid >> 5;

    __shared__ unsigned long long arr[2048];
    __shared__ int s_n;
    __shared__ int s_fs;
    __shared__ unsigned      s_last[NUM_CLASSES];
    __shared__ unsigned char s_opn[NUM_CLASSES];

    arr[tid] = 0ull;
    arr[tid + 1024] = 0ull;
    if (tid == 0) { s_n = 0; s_fs = 1 << 30; }
    __syncthreads();

    for (int c = wid; c < NUM_CLASSES; c += 32) {
        int idx = b * NUM_CLASSES + c;
        int cnt = g_pick_cnt[idx];
        int stk = g_pick_stk[idx];
        int base = 0;
        if (lane == 0) {
            base = atomicAdd(&s_n, cnt);
            s_last[c] = cnt ? __float_as_uint(g_pick_s[(size_t)idx * MAX_PER_IMG + cnt - 1]) : 0u;
            s_opn[c] = (unsigned char)g_open[idx];
        }
        base = __shfl_sync(0xFFFFFFFFu, base, 0);
        for (int p = lane; p < cnt; p += 32) {
            unsigned bits = __float_as_uint(g_pick_s[(size_t)idx * MAX_PER_IMG + p]);
            unsigned key  = (unsigned)g_pick_r[(size_t)idx * MAX_PER_IMG + p] * 80u + (unsigned)c;
            unsigned st   = (stk && p == cnt - 1) ? 1u : 0u;
            int pos = base + p;
            if (pos < 2048)
                arr[pos] = ((unsigned long long)bits << 32)
                         | (unsigned long long)(0xFFFFFFFFu - ((key << 1) | st));
        }
    }
    __syncthreads();

    // register-resident bitonic sort (descending), 2 elements per thread
    unsigned long long v0 = arr[2 * tid];
    unsigned long long v1 = arr[2 * tid + 1];
    #pragma unroll
    for (int k2 = 2; k2 <= 2048; k2 <<= 1) {
        bool desc = ((tid & (k2 >> 1)) == 0);
        for (int j = k2 >> 1; j >= 2; j >>= 1) {
            int hd = j >> 1;                       // partner thread distance
            bool lower = ((tid & hd) == 0);
            bool keepmax = (desc == lower);
            if (j >= 64) {
                arr[2 * tid] = v0;
                arr[2 * tid + 1] = v1;
                __syncthreads();
                unsigned long long o0 = arr[(2 * tid) ^ j];
                unsigned long long o1 = arr[(2 * tid + 1) ^ j];
                v0 = keepmax ? (v0 > o0 ? v0 : o0) : (v0 < o0 ? v0 : o0);
                v1 = keepmax ? (v1 > o1 ? v1 : o1) : (v1 < o1 ? v1 : o1);
                __syncthreads();
            } else {
                unsigned long long o0 = __shfl_xor_sync(0xFFFFFFFFu, v0, hd);
                unsigned long long o1 = __shfl_xor_sync(0xFFFFFFFFu, v1, hd);
                v0 = keepmax ? (v0 > o0 ? v0 : o0) : (v0 < o0 ? v0 : o0);
                v1 = keepmax ? (v1 > o1 ? v1 : o1) : (v1 < o1 ? v1 : o1);
            }
        }
        // j == 1: internal pair (2t lower, 2t+1 upper)
        unsigned long long hi = (v0 > v1) ? v0 : v1;
        unsigned long long lo = (v0 > v1) ? v1 : v0;
        v0 = desc ? hi : lo;
        v1 = desc ? lo : hi;
    }
    arr[2 * tid] = v0;
    arr[2 * tid + 1] = v1;
    __syncthreads();

    #pragma unroll
    for (int q = 0; q < 2; q++) {
        int i2 = tid + q * 1024;
        unsigned long long e = arr[i2];
        if (e != 0ull) {
            unsigned v = 0xFFFFFFFFu - (unsigned)(e & 0xFFFFFFFFull);
            if (v & 1u) atomicMin(&s_fs, i2);
        }
    }
    __syncthreads();

    int fs = s_fs;
    int ncand = s_n; if (ncand > 2048) ncand = 2048;

    float* outB = out + 8;
    float* outS = outB + B_IMG * MAX_PER_IMG * 4;
    float* outC = outS + B_IMG * MAX_PER_IMG;

    unsigned out100 = 0u;
    {
        int src99 = (99 <= fs) ? 99 : fs;
        bool has99 = (fs < 2048) ? true : (99 < ncand);
        if (has99) out100 = (unsigned)(arr[src99] >> 32);
    }

    if (tid < MAX_PER_IMG) {
        int t = tid;
        int src = (t <= fs) ? t : fs;
        bool has = (fs < 2048) ? true : (t < ncand);
        int o = b * MAX_PER_IMG + t;
        if (has) {
            unsigned long long e = arr[src];
            unsigned v = 0xFFFFFFFFu - (unsigned)(e & 0xFFFFFFFFull);
            unsigned key = v >> 1;
            int c = (int)(key % 80u);
            int r = (int)(key / 80u);
            float4 bx = g_boxes[b * 1024 + r];
            outB[o * 4 + 0] = bx.x;
            outB[o * 4 + 1] = bx.y;
            outB[o * 4 + 2] = bx.z;
            outB[o * 4 + 3] = bx.w;
            outS[o] = __uint_as_float((unsigned)(e >> 32));
            outC[o] = (float)c;
        } else {
            outB[o * 4 + 0] = 0.f; outB[o * 4 + 1] = 0.f;
            outB[o * 4 + 2] = 0.f; outB[o * 4 + 3] = 0.f;
            outS[o] = 0.f;
            outC[o] = -1.f;
        }
    }
    if (tid == 0) {
        int ndet = (fs < 2048) ? MAX_PER_IMG : (ncand < MAX_PER_IMG ? ncand : MAX_PER_IMG);
        out[b] = (float)ndet;
        if (!final_pass) g_out100[b] = out100;
    }

    if (!final_pass && tid < NUM_CLASSES) {
        int need = (s_opn[tid] && s_last[tid] >= out100) ? 1 : 0;
        g_need[b * NUM_CLASSES + tid] = need;
        if (need) g_redo = 1;
    }
}

// ---------------------------------------------------------------------------
// Launch
// ---------------------------------------------------------------------------
extern "C" void kernel_launch(void* const* d_in, const int* in_sizes, int n_in,
                              void* d_out, int out_size) {
    (void)in_sizes; (void)n_in; (void)out_size;
    Ptrs P;
    for (int i = 0; i < 20; i++) P.p[i] = (const float*)d_in[i];
    float* out = (float*)d_out;

    dim3 gp((NQUAD + 255) / 256, B_IMG, 4);
    k_maxscore_part<<<gp, 256>>>(P);
    dim3 gm((NQUAD + 255) / 256, B_IMG);
    k_mask<<<gm, 256>>>(P);
    k_select<<<B_IMG, 1024>>>(P);                          // top1000 + box/rowinfo
    k_classnms<<<dim3(NUM_CLASSES, B_IMG), 128>>>(P, 0);   // phase A (fused gather+dsigf)
    k_merge<<<B_IMG, 1024>>>(out, 0);                      // phase B (+ need/out100)
    k_classnms<<<dim3(NUM_CLASSES, B_IMG), 128>>>(P, 1);   // phase C (resume, early-stop)
    k_merge<<<B_IMG, 1024>>>(out, 1);                      // phase D (only if redo)
}

// round 17
// speedup vs baseline: 1.0927x; 1.0289x over previous
#include <cuda_runtime.h>
#include <cstdint>

// ---------------------------------------------------------------------------
// Problem constants
// ---------------------------------------------------------------------------
#define NUM_CLASSES 80
#define B_IMG 8
#define NTOT 20460            // total anchors per image across 5 levels
#define NQUAD 5115            // NTOT/4
#define TOPK 1000
#define MAX_PER_IMG 100
#define K_CAP 16              // phase-A per-class pick cap
#define IMG_H 768.0f
#define IMG_W 1280.0f
#define CLS_OFFSET 4096.0f
#define MAX_RATIO_ANCHOR 13.815510557964274f   // |log(1e-6)|
#define MAX_RATIO_BBOX   4.135166556742356f    // |log(16/1000)|

__device__ __constant__ int   c_HW[5]     = {15360, 3840, 960, 240, 60};
__device__ __constant__ int   c_W[5]      = {160, 80, 40, 20, 10};
__device__ __constant__ int   c_off[5]    = {0, 15360, 19200, 20160, 20400};
__device__ __constant__ int   c_qoff[5]   = {0, 3840, 4800, 5040, 5100};
__device__ __constant__ float c_stride[5] = {8.f, 16.f, 32.f, 64.f, 128.f};

// ---------------------------------------------------------------------------
// Scratch (device globals; no runtime allocation allowed)
// ---------------------------------------------------------------------------
__device__ float4   g_part[B_IMG * 4 * NQUAD];  // per-chunk class maxima
__device__ float4   g_key4[B_IMG * NQUAD];      // per-anchor masked max score
__device__ unsigned g_rowinfo[B_IMG * 1024];    // (mask<<31)|(level<<28)|local_r
__device__ float    g_sc[B_IMG * NUM_CLASSES * 1024]; // persisted suppressed state (open classes)
__device__ float4   g_boxes[B_IMG * 1024];      // decoded proposals

// per-class NMS pick lists
__device__ float          g_pick_s[B_IMG * NUM_CLASSES * MAX_PER_IMG];
__device__ unsigned short g_pick_r[B_IMG * NUM_CLASSES * MAX_PER_IMG];
__device__ int            g_pick_cnt[B_IMG * NUM_CLASSES];
__device__ int            g_pick_stk[B_IMG * NUM_CLASSES];
__device__ int            g_open[B_IMG * NUM_CLASSES];   // capped w/ state written back
__device__ int            g_need[B_IMG * NUM_CLASSES];   // merge-B: must deepen
__device__ unsigned       g_out100[B_IMG];               // bits of 100th output slot
__device__ int            g_redo;

struct Ptrs { const float* p[20]; };

// ---------------------------------------------------------------------------
// Numerics matching jax
// ---------------------------------------------------------------------------
__device__ __forceinline__ float sigf(float x) {
    if (x >= 0.f) return 1.f / (1.f + expf(-x));
    float e = expf(x);
    return e / (1.f + e);
}
__device__ __forceinline__ float dsigf(float x) {
    float s = sigf(x);
    return 1.f / (1.f + expf(-s));
}
__device__ __forceinline__ float clampf(float v, float lo, float hi) {
    return fminf(fmaxf(v, lo), hi);
}
// Exact predicate RN(num/den) > 0.5 without the divide (den > 0, num >= 0).
__device__ __forceinline__ bool iou_gt_half(float num, float den) {
    float h = 0.5f * den;
    if (num <= h) return false;
    if (num > h * 1.0000005f) return true;
    return (num / den > 0.5f);
}

// ---------------------------------------------------------------------------
// Kernel 1a: partial max over a 20-class chunk, 4 anchors/thread (LDG.128)
// ---------------------------------------------------------------------------
__global__ __launch_bounds__(256) void k_maxscore_part(Ptrs P) {
    if (blockIdx.x == 0 && blockIdx.y == 0 && blockIdx.z == 0 && threadIdx.x == 0)
        g_redo = 0;
    int b  = blockIdx.y;
    int ch = blockIdx.z;
    int q = blockIdx.x * 256 + threadIdx.x;
    if (q >= NQUAD) return;

    int l;
    if      (q < 3840) l = 0;
    else if (q < 4800) l = 1;
    else if (q < 5040) l = 2;
    else if (q < 5100) l = 3;
    else               l = 4;
    int rq  = q - c_qoff[l];
    int HW4 = c_HW[l] >> 2;

    float4 mx = make_float4(-3.402823466e38f, -3.402823466e38f,
                            -3.402823466e38f, -3.402823466e38f);
    const float4* cp = (const float4*)P.p[4 * l]
                     + ((size_t)b * NUM_CLASSES + ch * 20) * HW4 + rq;
    #pragma unroll 20
    for (int c = 0; c < 20; c++) {
        float4 v = cp[(size_t)c * HW4];
        mx.x = fmaxf(mx.x, v.x);
        mx.y = fmaxf(mx.y, v.y);
        mx.z = fmaxf(mx.z, v.z);
        mx.w = fmaxf(mx.w, v.w);
    }
    g_part[((size_t)b * 4 + ch) * NQUAD + q] = mx;
}

// ---------------------------------------------------------------------------
// Kernel 1b: combine 4 partial maxima + loc mask + double sigmoid -> key
// ---------------------------------------------------------------------------
__global__ __launch_bounds__(256) void k_mask(Ptrs P) {
    int b = blockIdx.y;
    int q = blockIdx.x * 256 + threadIdx.x;
    if (q >= NQUAD) return;

    int l;
    if      (q < 3840) l = 0;
    else if (q < 4800) l = 1;
    else if (q < 5040) l = 2;
    else if (q < 5100) l = 3;
    else               l = 4;
    int rq  = q - c_qoff[l];
    int HW4 = c_HW[l] >> 2;

    float4 m0 = g_part[((size_t)b * 4 + 0) * NQUAD + q];
    float4 m1 = g_part[((size_t)b * 4 + 1) * NQUAD + q];
    float4 m2 = g_part[((size_t)b * 4 + 2) * NQUAD + q];
    float4 m3 = g_part[((size_t)b * 4 + 3) * NQUAD + q];
    float4 mx;
    mx.x = fmaxf(fmaxf(m0.x, m1.x), fmaxf(m2.x, m3.x));
    mx.y = fmaxf(fmaxf(m0.y, m1.y), fmaxf(m2.y, m3.y));
    mx.z = fmaxf(fmaxf(m0.z, m1.z), fmaxf(m2.z, m3.z));
    mx.w = fmaxf(fmaxf(m0.w, m1.w), fmaxf(m2.w, m3.w));

    float4 lv = *((const float4*)P.p[4 * l + 3] + (size_t)b * HW4 + rq);
    float4 key;
    key.x = (sigf(lv.x) >= 0.01f) ? dsigf(mx.x) : 0.f;
    key.y = (sigf(lv.y) >= 0.01f) ? dsigf(mx.y) : 0.f;
    key.z = (sigf(lv.z) >= 0.01f) ? dsigf(mx.z) : 0.f;
    key.w = (sigf(lv.w) >= 0.01f) ? dsigf(mx.w) : 0.f;
    g_key4[(size_t)b * NQUAD + q] = key;
}

// ---------------------------------------------------------------------------
// Kernel 2: per-image top-1000 by (key desc, idx asc). 3-round radix select
// on the 22-bit key delta + count<1000 fallback, stable compaction, bitonic.
// EPILOGUE (fused): per selected row, decode proposal box + rowinfo.
// ---------------------------------------------------------------------------
__global__ __launch_bounds__(1024) void k_select(Ptrs P) {
    int b   = blockIdx.x;
    int tid = threadIdx.x;
    int lane = tid & 31, wid = tid >> 5;
    const unsigned* keys = reinterpret_cast<const unsigned*>(g_key4) + (size_t)b * NTOT;

    __shared__ unsigned hist[256];
    __shared__ unsigned sfx[256];
    __shared__ unsigned s_prefix;
    __shared__ int s_m;
    __shared__ int s_done;
    __shared__ unsigned long long sel[1024];
    __shared__ int warp_tot[32];
    __shared__ int warp_scan[32];
    __shared__ int s_fill;
    __shared__ int s_runeq;

    if (tid == 0) { s_prefix = 0u; s_m = TOPK; s_done = 0; }
    __syncthreads();

    const int SHIFTS[3] = {14, 6, 0};
    const unsigned BMASK[3] = {0xFFu, 0xFFu, 0x3Fu};

    for (int round = 0; round < 3; round++) {
        if (s_done) break;
        int shift = SHIFTS[round];
        if (tid < 256) hist[tid] = 0u;
        __syncthreads();
        unsigned pfx = s_prefix;
        unsigned pmask = (round == 0) ? 0u
                        : (round == 1 ? 0x3FC000u : 0x3FFFC0u);
        int mcur = s_m;
        for (int i = tid; i < 20480; i += 1024) {
            bool v = i < NTOT;
            unsigned k = v ? keys[i] : 0u;
            bool nz = v && (k != 0u);
            unsigned delta = k - 0x3F000000u;
            bool act = nz && ((delta & pmask) == pfx);
            unsigned bin = (delta >> shift) & BMASK[round];
            unsigned am = __ballot_sync(0xFFFFFFFFu, act);
            if (act) {
                unsigned peers = __match_any_sync(am, bin);
                if (lane == __ffs(peers) - 1)
                    atomicAdd(&hist[bin], (unsigned)__popc(peers));
            }
        }
        __syncthreads();
        if (wid == 0) {
            unsigned carry = 0;
            #pragma unroll
            for (int ch = 7; ch >= 0; ch--) {
                unsigned v = hist[ch * 32 + lane];
                #pragma unroll
                for (int d = 1; d < 32; d <<= 1) {
                    unsigned o = __shfl_down_sync(0xFFFFFFFFu, v, d);
                    if (lane + d < 32) v += o;
                }
                sfx[ch * 32 + lane] = v + carry;
                carry += __shfl_sync(0xFFFFFFFFu, v, 0);
            }
        }
        __syncthreads();
        if (round == 0 && tid == 0) {
            if (sfx[0] < (unsigned)TOPK) {
                s_prefix = 0xFFFFFFFFu;         // sentinel: T = 0
                s_m = TOPK - (int)sfx[0];
                s_done = 1;
            }
        }
        __syncthreads();
        if (s_done) break;
        if (tid < 256) {
            unsigned S = sfx[tid];
            unsigned above = S - hist[tid];
            if (S >= (unsigned)mcur && above < (unsigned)mcur) {
                s_prefix = pfx | ((unsigned)tid << shift);
                s_m = mcur - (int)above;
            }
        }
        __syncthreads();
    }

    unsigned T = (s_prefix == 0xFFFFFFFFu) ? 0u : (0x3F000000u + s_prefix);
    int meq = s_m;

    sel[tid] = 0ull;
    if (tid == 0) { s_fill = 0; s_runeq = 0; }
    __syncthreads();

    for (int base = 0; base < NTOT; base += 1024) {
        int i = base + tid;
        bool valid = i < NTOT;
        unsigned k = valid ? keys[i] : 0u;
        bool gt = valid && (k > T);
        bool eq = valid && (k == T);
        unsigned balgt = __ballot_sync(0xFFFFFFFFu, gt);
        if (balgt) {
            int leader = __ffs(balgt) - 1;
            int basep = 0;
            if (lane == leader) basep = atomicAdd(&s_fill, __popc(balgt));
            basep = __shfl_sync(0xFFFFFFFFu, basep, leader);
            if (gt) {
                int p = basep + __popc(balgt & ((1u << lane) - 1u));
                sel[p] = (((unsigned long long)k) << 32) |
                         (unsigned long long)(0xFFFFFFFFu - (unsigned)i);
            }
        }
        unsigned bal = __ballot_sync(0xFFFFFFFFu, eq);
        if (lane == 0) warp_tot[wid] = __popc(bal);
        __syncthreads();
        if (wid == 0) {
            int v = warp_tot[lane];
            #pragma unroll
            for (int d = 1; d < 32; d <<= 1) {
                int n = __shfl_up_sync(0xFFFFFFFFu, v, d);
                if (lane >= d) v += n;
            }
            warp_scan[lane] = v;
        }
        __syncthreads();
        int wbase = (wid == 0) ? 0 : warp_scan[wid - 1];
        int rank = s_runeq + wbase + __popc(bal & ((1u << lane) - 1u));
        if (eq && rank < meq) {
            int p = atomicAdd(&s_fill, 1);
            sel[p] = (((unsigned long long)k) << 32) |
                     (unsigned long long)(0xFFFFFFFFu - (unsigned)i);
        }
        __syncthreads();
        if (tid == 0) s_runeq += warp_scan[31];
        __syncthreads();
    }

    for (int k2 = 2; k2 <= 1024; k2 <<= 1) {
        for (int j = k2 >> 1; j > 0; j >>= 1) {
            __syncthreads();
            int ixj = tid ^ j;
            if (ixj > tid) {
                unsigned long long va = sel[tid], vb = sel[ixj];
                bool up = ((tid & k2) == 0);
                if (up ? (va < vb) : (va > vb)) { sel[tid] = vb; sel[ixj] = va; }
            }
        }
    }
    __syncthreads();
    int a = (int)(0xFFFFFFFFu - (unsigned)(sel[tid] & 0xFFFFFFFFull));

    // ---- epilogue: decode box + rowinfo for selected rows (tid < TOPK) ----
    if (tid < TOPK) {
        int l;
        if      (a < 15360) l = 0;
        else if (a < 19200) l = 1;
        else if (a < 20160) l = 2;
        else if (a < 20400) l = 3;
        else                l = 4;
        int r  = a - c_off[l];
        int HW = c_HW[l];
        int W  = c_W[l];
        int yi = r / W;
        int xi = r - yi * W;

        const float* bb  = P.p[4 * l + 1];
        const float* shp = P.p[4 * l + 2];
        const float* loc = P.p[4 * l + 3];

        unsigned mask = (sigf(loc[(size_t)b * HW + r]) >= 0.01f) ? 1u : 0u;
        g_rowinfo[b * 1024 + tid] = (mask << 31) | ((unsigned)l << 28) | (unsigned)r;

        float st = c_stride[l];
        float xx = (float)xi * st, yy = (float)yi * st;
        float pw = 4.f * st;
        float dw = clampf(shp[((size_t)b * 2 + 0) * HW + r], -MAX_RATIO_ANCHOR, MAX_RATIO_ANCHOR);
        float dh = clampf(shp[((size_t)b * 2 + 1) * HW + r], -MAX_RATIO_ANCHOR, MAX_RATIO_ANCHOR);
        float aw = pw * expf(dw);
        float ah = pw * expf(dh);
        float ax1 = xx - 0.5f * aw, ay1 = yy - 0.5f * ah;
        float ax2 = xx + 0.5f * aw, ay2 = yy + 0.5f * ah;
        float px = (ax1 + ax2) * 0.5f, py = (ay1 + ay2) * 0.5f;
        float w2 = ax2 - ax1,          h2 = ay2 - ay1;
        float dx  = bb[((size_t)b * 4 + 0) * HW + r];
        float dy  = bb[((size_t)b * 4 + 1) * HW + r];
        float dw2 = clampf(bb[((size_t)b * 4 + 2) * HW + r], -MAX_RATIO_BBOX, MAX_RATIO_BBOX);
        float dh2 = clampf(bb[((size_t)b * 4 + 3) * HW + r], -MAX_RATIO_BBOX, MAX_RATIO_BBOX);
        float gx = px + w2 * dx;
        float gy = py + h2 * dy;
        float gw = w2 * expf(dw2);
        float gh = h2 * expf(dh2);
        float x1 = clampf(gx - 0.5f * gw, 0.f, IMG_W);
        float y1 = clampf(gy - 0.5f * gh, 0.f, IMG_H);
        float x2 = clampf(gx + 0.5f * gw, 0.f, IMG_W);
        float y2 = clampf(gy + 0.5f * gh, 0.f, IMG_H);
        g_boxes[b * 1024 + tid] = make_float4(x1, y1, x2, y2);
    }
}

// ---------------------------------------------------------------------------
// Kernel 3: per-class greedy NMS with FUSED score gather. 256 threads per
// (image, class); each thread owns 4 entries (j = tid + 256*k) -- 8 warps
// per block feeds the MUFU pipe during the fused dsigf init and doubles
// latency hiding in the serial rounds (isolated from R15's confounded pair).
// mode 0 (phase A): gather raw cls logits (L2-resident after k_maxscore) and
// compute s = dsigf(v) inline (thresholded, masked). Cap K_CAP; if capped
// ("open"), persist suppressed scores to g_sc so phase C resumes exactly.
// mode 1 (phase C): only needed classes; load persisted state from g_sc;
// EARLY-STOP when the next pick's score bits drop below g_out100[b].
// Argmax: nonzero scores in (0.5, 0.7312) -> (bits-0x3F000000)<<10 | (1023-j)
// gives (score desc, j asc) in ONE __reduce_max_sync. Suppression predicate
// division-free (iou_gt_half). Sticky degenerate picks recorded & stopped.
// ---------------------------------------------------------------------------
__global__ __launch_bounds__(256) void k_classnms(Ptrs P, int mode) {
    int c = blockIdx.x;
    int b = blockIdx.y;
    int idx = b * NUM_CLASSES + c;
    if (mode == 1 && (g_redo == 0 || g_need[idx] == 0)) return;
    int tid = threadIdx.x;
    int lane = tid & 31, wid = tid >> 5;

    __shared__ float4 sbox[TOPK];
    __shared__ float  sarea[TOPK];
    __shared__ unsigned char sdeg[TOPK];   // 1 = degenerate (survives self)
    __shared__ unsigned wtop[2][8];

    float offc = CLS_OFFSET * (float)c;
    unsigned stop_delta = 0u;
    if (mode == 1) {
        unsigned ob = g_out100[b];
        stop_delta = (ob > 0x3F000000u) ? (ob - 0x3F000000u) : 0u;
    }

    float4  rb[4];
    float   ra[4];
    unsigned comp[4];                  // (bits-0x3F000000)<<10 | (1023-j); 0 = dead
    float* sp = g_sc + ((size_t)idx) * 1024;
    #pragma unroll
    for (int k = 0; k < 4; k++) {
        int j = tid + 256 * k;
        float4 q = (j < TOPK) ? g_boxes[b * 1024 + j] : make_float4(0.f, 0.f, 0.f, 0.f);
        q.x += offc; q.y += offc; q.z += offc; q.w += offc;
        float ar = (q.z - q.x) * (q.w - q.y);
        rb[k] = q; ra[k] = ar;
        if (j < TOPK) {
            sbox[j] = q; sarea[j] = ar;
            sdeg[j] = iou_gt_half(ar, ar + 1e-6f) ? 0 : 1;
        }
        float s = 0.f;
        if (j < TOPK) {
            if (mode == 0) {
                unsigned info = g_rowinfo[b * 1024 + j];
                if (info >> 31) {
                    int l = (info >> 28) & 7;
                    int r = (int)(info & 0x0FFFFFFFu);
                    float v = P.p[4 * l][((size_t)b * NUM_CLASSES + c) * c_HW[l] + r];
                    s = dsigf(v);
                    if (!(s > 0.05f)) s = 0.f;
                }
            } else {
                s = sp[j];
            }
        }
        unsigned bits = __float_as_uint(s);
        comp[k] = (bits > 0x3F000000u)
                ? (((bits - 0x3F000000u) << 10) | (unsigned)(1023 - j)) : 0u;
    }
    __syncthreads();

    int cap = (mode == 1) ? MAX_PER_IMG : K_CAP;
    int cnt = (mode == 1) ? g_pick_cnt[idx] : 0;
    float*          ps = g_pick_s + (size_t)idx * MAX_PER_IMG;
    unsigned short* pr = g_pick_r + (size_t)idx * MAX_PER_IMG;

    int sticky = 0, open = 0, rnd = 0;

    for (;;) {
        unsigned c1 = 0u;
        #pragma unroll
        for (int k = 0; k < 4; k++) c1 = max(c1, comp[k]);
        unsigned M = __reduce_max_sync(0xFFFFFFFFu, c1);
        if (lane == 0) wtop[rnd & 1][wid] = M;
        __syncthreads();
        unsigned M1 = max(max(max(wtop[rnd & 1][0], wtop[rnd & 1][1]),
                              max(wtop[rnd & 1][2], wtop[rnd & 1][3])),
                          max(max(wtop[rnd & 1][4], wtop[rnd & 1][5]),
                              max(wtop[rnd & 1][6], wtop[rnd & 1][7])));
        rnd++;
        if (M1 == 0u) break;                                // class exhausted
        if (mode == 1 && (M1 >> 10) < stop_delta) break;    // provably irrelevant
        if (cnt == cap) { open = 1; break; }                // capped (pending)

        int j1 = 1023 - (int)(M1 & 1023u);
        if (tid == 0) {
            ps[cnt] = __uint_as_float((M1 >> 10) + 0x3F000000u);
            pr[cnt] = (unsigned short)j1;
        }
        cnt++;
        if (sdeg[j1]) { sticky = 1; break; }                // survives itself

        float4 p1 = sbox[j1];
        float ar1 = sarea[j1];
        #pragma unroll
        for (int k = 0; k < 4; k++) {
            if (comp[k] != 0u) {
                float4 q = rb[k];
                float ltx = fmaxf(p1.x, q.x), lty = fmaxf(p1.y, q.y);
                float rbx = fminf(p1.z, q.z), rby = fminf(p1.w, q.w);
                float ww = fmaxf(rbx - ltx, 0.f), hh = fmaxf(rby - lty, 0.f);
                float inter = ww * hh;
                float den = ar1 + ra[k] - inter + 1e-6f;
                if (iou_gt_half(inter, den)) comp[k] = 0u;
            }
        }
    }

    // open classes persist suppressed state so phase C can resume exactly
    if (mode == 0 && open) {
        #pragma unroll
        for (int k = 0; k < 4; k++) {
            int j = tid + 256 * k;
            if (j < TOPK)
                sp[j] = comp[k] ? __uint_as_float((comp[k] >> 10) + 0x3F000000u) : 0.f;
        }
    }

    if (tid == 0) {
        g_pick_cnt[idx] = cnt;
        g_pick_stk[idx] = sticky;
        g_open[idx] = (mode == 0) ? open : 0;
    }
}

// ---------------------------------------------------------------------------
// Kernel 4: per-image merge as a SORT. Bitonic over 2048 with elements
// REGISTER-RESIDENT (thread t owns indices 2t, 2t+1): j==1 is thread-
// internal, j in {2..32} uses warp shuffles, only j>=64 touches smem.
// First sticky in sorted order repeats forever (sticky bit in low word).
// Phase B (final=0): need[c] = open[c] && last_bits >= bits(100th output);
// stores bits(100th output) in g_out100[b]. Phase D (final=1): only if redo.
// ---------------------------------------------------------------------------
__global__ __launch_bounds__(1024) void k_merge(float* __restrict__ out, int final_pass) {
    if (final_pass && g_redo == 0) return;
    int b = blockIdx.x;
    int tid = threadIdx.x;
    int lane = tid & 31, wid = tid >> 5;

    __shared__ unsigned long long arr[2048];
    __shared__ int s_n;
    __shared__ int s_fs;
    __shared__ unsigned      s_last[NUM_CLASSES];
    __shared__ unsigned char s_opn[NUM_CLASSES];

    arr[tid] = 0ull;
    arr[tid + 1024] = 0ull;
    if (tid == 0) { s_n = 0; s_fs = 1 << 30; }
    __syncthreads();

    for (int c = wid; c < NUM_CLASSES; c += 32) {
        int idx = b * NUM_CLASSES + c;
        int cnt = g_pick_cnt[idx];
        int stk = g_pick_stk[idx];
        int base = 0;
        if (lane == 0) {
            base = atomicAdd(&s_n, cnt);
            s_last[c] = cnt ? __float_as_uint(g_pick_s[(size_t)idx * MAX_PER_IMG + cnt - 1]) : 0u;
            s_opn[c] = (unsigned char)g_open[idx];
        }
        base = __shfl_sync(0xFFFFFFFFu, base, 0);
        for (int p = lane; p < cnt; p += 32) {
            unsigned bits = __float_as_uint(g_pick_s[(size_t)idx * MAX_PER_IMG + p]);
            unsigned key  = (unsigned)g_pick_r[(size_t)idx * MAX_PER_IMG + p] * 80u + (unsigned)c;
            unsigned st   = (stk && p == cnt - 1) ? 1u : 0u;
            int pos = base + p;
            if (pos < 2048)
                arr[pos] = ((unsigned long long)bits << 32)
                         | (unsigned long long)(0xFFFFFFFFu - ((key << 1) | st));
        }
    }
    __syncthreads();

    // register-resident bitonic sort (descending), 2 elements per thread
    unsigned long long v0 = arr[2 * tid];
    unsigned long long v1 = arr[2 * tid + 1];
    #pragma unroll
    for (int k2 = 2; k2 <= 2048; k2 <<= 1) {
        bool desc = ((tid & (k2 >> 1)) == 0);
        for (int j = k2 >> 1; j >= 2; j >>= 1) {
            int hd = j >> 1;                       // partner thread distance
            bool lower = ((tid & hd) == 0);
            bool keepmax = (desc == lower);
            if (j >= 64) {
                arr[2 * tid] = v0;
                arr[2 * tid + 1] = v1;
                __syncthreads();
                unsigned long long o0 = arr[(2 * tid) ^ j];
                unsigned long long o1 = arr[(2 * tid + 1) ^ j];
                v0 = keepmax ? (v0 > o0 ? v0 : o0) : (v0 < o0 ? v0 : o0);
                v1 = keepmax ? (v1 > o1 ? v1 : o1) : (v1 < o1 ? v1 : o1);
                __syncthreads();
            } else {
                unsigned long long o0 = __shfl_xor_sync(0xFFFFFFFFu, v0, hd);
                unsigned long long o1 = __shfl_xor_sync(0xFFFFFFFFu, v1, hd);
                v0 = keepmax ? (v0 > o0 ? v0 : o0) : (v0 < o0 ? v0 : o0);
                v1 = keepmax ? (v1 > o1 ? v1 : o1) : (v1 < o1 ? v1 : o1);
            }
        }
        // j == 1: internal pair (2t lower, 2t+1 upper)
        unsigned long long hi = (v0 > v1) ? v0 : v1;
        unsigned long long lo = (v0 > v1) ? v1 : v0;
        v0 = desc ? hi : lo;
        v1 = desc ? lo : hi;
    }
    arr[2 * tid] = v0;
    arr[2 * tid + 1] = v1;
    __syncthreads();

    #pragma unroll
    for (int q = 0; q < 2; q++) {
        int i2 = tid + q * 1024;
        unsigned long long e = arr[i2];
        if (e != 0ull) {
            unsigned v = 0xFFFFFFFFu - (unsigned)(e & 0xFFFFFFFFull);
            if (v & 1u) atomicMin(&s_fs, i2);
        }
    }
    __syncthreads();

    int fs = s_fs;
    int ncand = s_n; if (ncand > 2048) ncand = 2048;

    float* outB = out + 8;
    float* outS = outB + B_IMG * MAX_PER_IMG * 4;
    float* outC = outS + B_IMG * MAX_PER_IMG;

    unsigned out100 = 0u;
    {
        int src99 = (99 <= fs) ? 99 : fs;
        bool has99 = (fs < 2048) ? true : (99 < ncand);
        if (has99) out100 = (unsigned)(arr[src99] >> 32);
    }

    if (tid < MAX_PER_IMG) {
        int t = tid;
        int src = (t <= fs) ? t : fs;
        bool has = (fs < 2048) ? true : (t < ncand);
        int o = b * MAX_PER_IMG + t;
        if (has) {
            unsigned long long e = arr[src];
            unsigned v = 0xFFFFFFFFu - (unsigned)(e & 0xFFFFFFFFull);
            unsigned key = v >> 1;
            int c = (int)(key % 80u);
            int r = (int)(key / 80u);
            float4 bx = g_boxes[b * 1024 + r];
            outB[o * 4 + 0] = bx.x;
            outB[o * 4 + 1] = bx.y;
            outB[o * 4 + 2] = bx.z;
            outB[o * 4 + 3] = bx.w;
            outS[o] = __uint_as_float((unsigned)(e >> 32));
            outC[o] = (float)c;
        } else {
            outB[o * 4 + 0] = 0.f; outB[o * 4 + 1] = 0.f;
            outB[o * 4 + 2] = 0.f; outB[o * 4 + 3] = 0.f;
            outS[o] = 0.f;
            outC[o] = -1.f;
        }
    }
    if (tid == 0) {
        int ndet = (fs < 2048) ? MAX_PER_IMG : (ncand < MAX_PER_IMG ? ncand : MAX_PER_IMG);
        out[b] = (float)ndet;
        if (!final_pass) g_out100[b] = out100;
    }

    if (!final_pass && tid < NUM_CLASSES) {
        int need = (s_opn[tid] && s_last[tid] >= out100) ? 1 : 0;
        g_need[b * NUM_CLASSES + tid] = need;
        if (need) g_redo = 1;
    }
}

// ---------------------------------------------------------------------------
// Launch
// ---------------------------------------------------------------------------
extern "C" void kernel_launch(void* const* d_in, const int* in_sizes, int n_in,
                              void* d_out, int out_size) {
    (void)in_sizes; (void)n_in; (void)out_size;
    Ptrs P;
    for (int i = 0; i < 20; i++) P.p[i] = (const float*)d_in[i];
    float* out = (float*)d_out;

    dim3 gp((NQUAD + 255) / 256, B_IMG, 4);
    k_maxscore_part<<<gp, 256>>>(P);
    dim3 gm((NQUAD + 255) / 256, B_IMG);
    k_mask<<<gm, 256>>>(P);
    k_select<<<B_IMG, 1024>>>(P);                          // top1000 + box/rowinfo
    k_classnms<<<dim3(NUM_CLASSES, B_IMG), 256>>>(P, 0);   // phase A (fused gather+dsigf)
    k_merge<<<B_IMG, 1024>>>(out, 0);                      // phase B (+ need/out100)
    k_classnms<<<dim3(NUM_CLASSES, B_IMG), 256>>>(P, 1);   // phase C (resume, early-stop)
    k_merge<<<B_IMG, 1024>>>(out, 1);                      // phase D (only if redo)
}